// round 5
// baseline (speedup 1.0000x reference)
#include <cuda_runtime.h>
#include <math.h>

// Fixed problem shape
#define NMAX 100000
#define QMAX 256
#define RMAX 401
#define BM   128

typedef unsigned long long u64;

// Scratch (device globals — no allocation allowed)
__device__ float g_tableS[NMAX * 64];           // Ws·hidden + Ws_b          (25.6 MB)
__device__ float g_tableR[RMAX * 64];           // Wr·rela
__device__ float g_tableQ[QMAX * 64];           // Wq·q_emb
__device__ float g_tableQR[QMAX * RMAX * 64];   // Wqr·(rela⊙q) + tR + tQ    (26.3 MB)
__device__ float g_agg[NMAX * 64];              // segment-sum accumulator   (25.6 MB)

// ---- packed f32x2 helpers (sm_103a FFMA2) ----
__device__ __forceinline__ u64 ffma2(u64 a, u64 b, u64 c) {
    u64 d;
    asm("fma.rn.f32x2 %0, %1, %2, %3;" : "=l"(d) : "l"(a), "l"(b), "l"(c));
    return d;
}
__device__ __forceinline__ u64 splat2(float x) {
    u64 d;
    unsigned u = __float_as_uint(x);
    asm("mov.b64 %0, {%1, %1};" : "=l"(d) : "r"(u));
    return d;
}
__device__ __forceinline__ u64 pack2(float lo, float hi) {
    u64 d;
    asm("mov.b64 %0, {%1, %2};" : "=l"(d) : "r"(__float_as_uint(lo)), "r"(__float_as_uint(hi)));
    return d;
}
__device__ __forceinline__ float2 unpack2(u64 v) {
    unsigned lo, hi;
    asm("mov.b64 {%0, %1}, %2;" : "=r"(lo), "=r"(hi) : "l"(v));
    return make_float2(__uint_as_float(lo), __uint_as_float(hi));
}

// Core 4x8 FFMA2 mainloop. acc[i][j]: row i (of 4), col-pair j (of 4).
__device__ __forceinline__ void mainloop_4x8(const float* __restrict__ Wt,
                                             const float* __restrict__ Xs,
                                             int r0, int a0, u64 acc[4][4])
{
    #pragma unroll
    for (int d = 0; d < 64; d += 4) {
        float4 xv[4];
        #pragma unroll
        for (int i = 0; i < 4; i++)
            xv[i] = *(const float4*)&Xs[(r0 + i) * 64 + d];
        #pragma unroll
        for (int k = 0; k < 4; k++) {
            ulonglong2 wA = *(const ulonglong2*)&Wt[(d + k) * 64 + a0];
            ulonglong2 wB = *(const ulonglong2*)&Wt[(d + k) * 64 + a0 + 4];
            #pragma unroll
            for (int i = 0; i < 4; i++) {
                float xs = (k == 0) ? xv[i].x : (k == 1) ? xv[i].y
                         : (k == 2) ? xv[i].z : xv[i].w;
                u64 s = splat2(xs);
                acc[i][0] = ffma2(s, wA.x, acc[i][0]);
                acc[i][1] = ffma2(s, wA.y, acc[i][1]);
                acc[i][2] = ffma2(s, wB.x, acc[i][2]);
                acc[i][3] = ffma2(s, wB.y, acc[i][3]);
            }
        }
    }
}

// -----------------------------------------------------------------------------
// GEMM (NT): out[m,a] = sum_d X[m,d] * W[a,d] (+ bias[a]).  D = A = 64.
// BM=128 rows/block, 256 threads, 4x8 thread tile, FFMA2, 48 KB smem ->
// 3-4 CTAs/SM (24-32 warps) to keep the fma pipe fed.
// -----------------------------------------------------------------------------
__global__ __launch_bounds__(256, 3)
void gemm_nt_kernel(const float* __restrict__ X,
                    const float* __restrict__ W,
                    const float* __restrict__ bias,
                    float* __restrict__ out, int M,
                    float4* __restrict__ zbuf)
{
    extern __shared__ float smem[];
    float* Wt = smem;              // [64][64]  Wt[d*64+a] = W[a*64+d]
    float* Xs = smem + 4096;       // [BM][64]
    const int tid = threadIdx.x;
    const int m0 = blockIdx.x * BM;

    #pragma unroll
    for (int i = tid; i < 4096; i += 256)
        Wt[i] = W[((i & 63) << 6) | (i >> 6)];

    #pragma unroll
    for (int i = tid; i < BM * 16; i += 256) {
        int row = i >> 4;
        float4 v = make_float4(0.f, 0.f, 0.f, 0.f);
        if (m0 + row < M) v = __ldg(&((const float4*)X)[(size_t)(m0 + row) * 16 + (i & 15)]);
        ((float4*)Xs)[i] = v;
    }
    if (zbuf) {
        #pragma unroll
        for (int i = tid; i < BM * 16; i += 256) {
            int row = i >> 4;
            if (m0 + row < M)
                zbuf[(size_t)(m0 + row) * 16 + (i & 15)] = make_float4(0.f, 0.f, 0.f, 0.f);
        }
    }
    __syncthreads();

    const int a0 = (tid & 7) * 8;
    const int r0 = (tid >> 3) * 4;

    u64 acc[4][4];
    {
        u64 b0 = 0, b1 = 0, b2 = 0, b3 = 0;
        if (bias) {
            float4 bA = *(const float4*)&bias[a0];
            float4 bB = *(const float4*)&bias[a0 + 4];
            b0 = pack2(bA.x, bA.y); b1 = pack2(bA.z, bA.w);
            b2 = pack2(bB.x, bB.y); b3 = pack2(bB.z, bB.w);
        }
        #pragma unroll
        for (int i = 0; i < 4; i++) {
            acc[i][0] = b0; acc[i][1] = b1; acc[i][2] = b2; acc[i][3] = b3;
        }
    }

    mainloop_4x8(Wt, Xs, r0, a0, acc);

    #pragma unroll
    for (int i = 0; i < 4; i++) {
        int row = m0 + r0 + i;
        if (row < M) {
            *(ulonglong2*)&out[(size_t)row * 64 + a0]     = make_ulonglong2(acc[i][0], acc[i][1]);
            *(ulonglong2*)&out[(size_t)row * 64 + a0 + 4] = make_ulonglong2(acc[i][2], acc[i][3]);
        }
    }
}

// -----------------------------------------------------------------------------
// QR GEMM: row p=(q,r): X = q_emb[q] ⊙ rela[r]; out = X·Wqr^T + tR[r] + tQ[q]
// -----------------------------------------------------------------------------
__global__ __launch_bounds__(256, 3)
void gemm_qr_kernel(const float* __restrict__ qe,
                    const float* __restrict__ re,
                    const float* __restrict__ W,
                    const float* __restrict__ tR,
                    const float* __restrict__ tQ,
                    float* __restrict__ out, int M, int R)
{
    extern __shared__ float smem[];
    float* Wt = smem;
    float* Xs = smem + 4096;
    const int tid = threadIdx.x;
    const int m0 = blockIdx.x * BM;

    #pragma unroll
    for (int i = tid; i < 4096; i += 256)
        Wt[i] = W[((i & 63) << 6) | (i >> 6)];

    #pragma unroll
    for (int i = tid; i < BM * 16; i += 256) {
        int row = i >> 4, c4 = i & 15;
        float4 v = make_float4(0.f, 0.f, 0.f, 0.f);
        int p = m0 + row;
        if (p < M) {
            int q = p / R;
            int r = p - q * R;
            float4 a = __ldg(&((const float4*)qe)[q * 16 + c4]);
            float4 b = __ldg(&((const float4*)re)[r * 16 + c4]);
            v = make_float4(a.x * b.x, a.y * b.y, a.z * b.z, a.w * b.w);
        }
        ((float4*)Xs)[i] = v;
    }
    __syncthreads();

    const int a0 = (tid & 7) * 8;
    const int r0 = (tid >> 3) * 4;

    u64 acc[4][4];
    #pragma unroll
    for (int i = 0; i < 4; i++)
        acc[i][0] = acc[i][1] = acc[i][2] = acc[i][3] = 0ull;

    mainloop_4x8(Wt, Xs, r0, a0, acc);

    #pragma unroll
    for (int i = 0; i < 4; i++) {
        int p = m0 + r0 + i;
        if (p < M) {
            int q = p / R;
            int r = p - q * R;
            float4 tA = __ldg(&((const float4*)tR)[r * 16 + (a0 >> 2)]);
            float4 tB = __ldg(&((const float4*)tR)[r * 16 + (a0 >> 2) + 1]);
            float4 uA = __ldg(&((const float4*)tQ)[q * 16 + (a0 >> 2)]);
            float4 uB = __ldg(&((const float4*)tQ)[q * 16 + (a0 >> 2) + 1]);
            float2 v0 = unpack2(acc[i][0]);
            float2 v1 = unpack2(acc[i][1]);
            float2 v2 = unpack2(acc[i][2]);
            float2 v3 = unpack2(acc[i][3]);
            float4 oA = make_float4(v0.x + tA.x + uA.x, v0.y + tA.y + uA.y,
                                    v1.x + tA.z + uA.z, v1.y + tA.w + uA.w);
            float4 oB = make_float4(v2.x + tB.x + uB.x, v2.y + tB.y + uB.y,
                                    v3.x + tB.z + uB.z, v3.y + tB.w + uB.w);
            *(float4*)&out[(size_t)p * 64 + a0]     = oA;
            *(float4*)&out[(size_t)p * 64 + a0 + 4] = oB;
        }
    }
}

// -----------------------------------------------------------------------------
// Edge kernel: half-warp (16 lanes) per edge, float4 per lane.
// -----------------------------------------------------------------------------
__global__ __launch_bounds__(256)
void edge_kernel(const int* __restrict__ edges,
                 const float* __restrict__ hidden,
                 const float* __restrict__ rela,
                 const float* __restrict__ wa_W,
                 const float* __restrict__ wa_b,
                 const float* __restrict__ tS,
                 const float* __restrict__ tQR,
                 float* __restrict__ agg,
                 float* __restrict__ alpha_out,
                 int E, int R)
{
    const int t = blockIdx.x * 256 + threadIdx.x;
    const int e = t >> 4;
    if (e >= E) return;
    const int sl = t & 15;

    const int* er = edges + (size_t)e * 6;
    const int q = __ldg(er + 0);
    const int r = __ldg(er + 2);
    const int s = __ldg(er + 4);
    const int o = __ldg(er + 5);

    float4 g   = __ldg(&((const float4*)tS)[(size_t)s * 16 + sl]);
    float4 p2  = __ldg(&((const float4*)tQR)[((size_t)q * R + r) * 16 + sl]);
    float4 hs  = __ldg(&((const float4*)hidden)[(size_t)s * 16 + sl]);
    float4 hr  = __ldg(&((const float4*)rela)[(size_t)r * 16 + sl]);
    float4 wa  = __ldg(&((const float4*)wa_W)[sl]);

    float px = fmaxf(g.x + p2.x, 0.f);
    float py = fmaxf(g.y + p2.y, 0.f);
    float pz = fmaxf(g.z + p2.z, 0.f);
    float pw = fmaxf(g.w + p2.w, 0.f);

    float part = fmaf(px, wa.x, fmaf(py, wa.y, fmaf(pz, wa.z, pw * wa.w)));
    #pragma unroll
    for (int off = 8; off; off >>= 1)
        part += __shfl_xor_sync(0xffffffffu, part, off);

    float alpha = 1.0f / (1.0f + __expf(-(part + __ldg(wa_b))));
    if (sl == 0) alpha_out[e] = alpha;

    float4 m;
    m.x = alpha * hs.x * hr.x;
    m.y = alpha * hs.y * hr.y;
    m.z = alpha * hs.z * hr.z;
    m.w = alpha * hs.w * hr.w;

    float* dst = &agg[(size_t)o * 64 + sl * 4];
    asm volatile("red.global.add.v4.f32 [%0], {%1, %2, %3, %4};"
                 :: "l"(dst), "f"(m.x), "f"(m.y), "f"(m.z), "f"(m.w) : "memory");
}

// -----------------------------------------------------------------------------
extern "C" void kernel_launch(void* const* d_in, const int* in_sizes, int n_in,
                              void* d_out, int out_size)
{
    const float* q_emb  = (const float*)d_in[1];
    const float* rela   = (const float*)d_in[2];
    const float* hidden = (const float*)d_in[3];
    const int*   edges  = (const int*)d_in[4];
    const float* Ws_W   = (const float*)d_in[6];
    const float* Ws_b   = (const float*)d_in[7];
    const float* Wr_W   = (const float*)d_in[8];
    const float* Wq_W   = (const float*)d_in[9];
    const float* Wqr_W  = (const float*)d_in[10];
    const float* wa_W   = (const float*)d_in[11];
    const float* wa_b   = (const float*)d_in[12];
    const float* Wh_W   = (const float*)d_in[13];

    const int Q = in_sizes[0];
    const int R = in_sizes[2] / 64;
    const int N = in_sizes[3] / 64;
    const int E = in_sizes[4] / 6;

    float* out = (float*)d_out;
    float* alpha_out = out + (size_t)N * 64;

    float *tS, *tR, *tQ, *tQR, *agg;
    cudaGetSymbolAddress((void**)&tS,  g_tableS);
    cudaGetSymbolAddress((void**)&tR,  g_tableR);
    cudaGetSymbolAddress((void**)&tQ,  g_tableQ);
    cudaGetSymbolAddress((void**)&tQR, g_tableQR);
    cudaGetSymbolAddress((void**)&agg, g_agg);

    const int SMEM = (4096 + BM * 64) * 4;   // Wt + Xs = 48 KB
    cudaFuncSetAttribute(gemm_nt_kernel, cudaFuncAttributeMaxDynamicSharedMemorySize, SMEM);
    cudaFuncSetAttribute(gemm_qr_kernel, cudaFuncAttributeMaxDynamicSharedMemorySize, SMEM);

    // Small tables first (inputs to the QR fold)
    gemm_nt_kernel<<<(R + BM - 1) / BM, 256, SMEM>>>(rela,  Wr_W, nullptr, tR, R, nullptr);
    gemm_nt_kernel<<<(Q + BM - 1) / BM, 256, SMEM>>>(q_emb, Wq_W, nullptr, tQ, Q, nullptr);

    // Big precomputes (tS pass also zeroes agg rows)
    gemm_nt_kernel<<<(N + BM - 1) / BM, 256, SMEM>>>(hidden, Ws_W, Ws_b, tS, N, (float4*)agg);
    gemm_qr_kernel<<<(Q * R + BM - 1) / BM, 256, SMEM>>>(q_emb, rela, Wqr_W, tR, tQ,
                                                         tQR, Q * R, R);

    // Per-edge gather/gate/scatter (half-warp per edge)
    edge_kernel<<<(E * 16 + 255) / 256, 256>>>(edges, hidden, rela, wa_W, wa_b,
                                               tS, tQR, agg, alpha_out, E, R);

    // Final projection: hidden_new = agg @ Wh^T
    gemm_nt_kernel<<<(N + BM - 1) / BM, 256, SMEM>>>(agg, Wh_W, nullptr, out, N, nullptr);
}

// round 6
// speedup vs baseline: 1.1381x; 1.1381x over previous
#include <cuda_runtime.h>
#include <math.h>

// Fixed problem shape
#define NMAX 100000
#define QMAX 256
#define RMAX 401

typedef unsigned long long u64;

// Scratch (device globals — no allocation allowed)
__device__ float g_tableS[NMAX * 64];           // Ws·hidden + Ws_b          (25.6 MB)
__device__ float g_tableR[RMAX * 64];           // Wr·rela
__device__ float g_tableQ[QMAX * 64];           // Wq·q_emb
__device__ float g_tableQR[QMAX * RMAX * 64];   // Wqr·(rela⊙q) + tR + tQ    (26.3 MB)
__device__ float g_agg[NMAX * 64];              // segment-sum accumulator   (25.6 MB)

// ---- packed f32x2 helpers (sm_103a FFMA2 / FADD2) ----
__device__ __forceinline__ u64 ffma2(u64 a, u64 b, u64 c) {
    u64 d;
    asm("fma.rn.f32x2 %0, %1, %2, %3;" : "=l"(d) : "l"(a), "l"(b), "l"(c));
    return d;
}
__device__ __forceinline__ u64 addf32x2(u64 a, u64 b) {
    u64 d;
    asm("add.rn.f32x2 %0, %1, %2;" : "=l"(d) : "l"(a), "l"(b));
    return d;
}
__device__ __forceinline__ u64 pack2(float lo, float hi) {
    u64 d;
    asm("mov.b64 %0, {%1, %2};" : "=l"(d) : "r"(__float_as_uint(lo)), "r"(__float_as_uint(hi)));
    return d;
}

// -----------------------------------------------------------------------------
// 64x64 NT GEMM, W-in-registers / broadcast-X design.
//   out[m, a] = sum_d X[m,d] * W[a,d]  (+ epilogue)
// Block: 256 thr = 8 warps. Warp w: k-half h = w&1, row-group rg = w>>1.
// Lane l owns column pair (2l, 2l+1); Wr[32] u64 regs = W[2l:2l+2, h*32:h*32+32].
// X staged in smem pre-splatted ({x,x} u64) -> mainloop = broadcast LDS.128
// + 2 FFMA2, no ALU splats. Partial k-halves combined via smem + add.f32x2.
// MODE 0: X from gmem, optional bias, optional zbuf zeroing (fused agg clear).
// MODE 1: X row p=(q,r) formed as q_emb[q]⊙rela[r]; epilogue adds tR[r]+tQ[q].
// -----------------------------------------------------------------------------
template<int MODE>
__global__ __launch_bounds__(256, 2)
void gemm64(const float* __restrict__ X,
            const float* __restrict__ qe,
            const float* __restrict__ re,
            const float* __restrict__ W,
            const float* __restrict__ bias,
            const float* __restrict__ tR,
            const float* __restrict__ tQ,
            float* __restrict__ out, int M, int R,
            float4* __restrict__ zbuf)
{
    extern __shared__ u64 sm[];
    u64* Wt2 = sm;                 // [64 d][32 lanes]   16 KB
    u64* Xs  = sm + 64 * 32;       // [64 rows][64 d]    32 KB (splat-dup)
    u64* Ps  = sm + 64 * 32 + 64 * 64;  // [64 rows][2 h][32 l]  32 KB

    const int tid  = threadIdx.x;
    const int lane = tid & 31;
    const int w    = tid >> 5;
    const int h    = w & 1;
    const int rg   = w >> 1;

    // Stage W transposed into pair layout: Wt2[d][l] = {W[2l][d], W[2l+1][d]}
    for (int i = tid; i < 2048; i += 256) {
        int d = i >> 5, l = i & 31;
        Wt2[i] = pack2(__ldg(&W[(2 * l) * 64 + d]), __ldg(&W[(2 * l + 1) * 64 + d]));
    }
    __syncthreads();

    // Load this thread's W half into registers (persistent across batches)
    u64 Wr[32];
    #pragma unroll
    for (int j = 0; j < 32; j++)
        Wr[j] = Wt2[(h * 32 + j) * 32 + lane];

    for (int m0 = blockIdx.x * 64; m0 < M; m0 += gridDim.x * 64) {
        __syncthreads();   // Xs/Ps safe to overwrite (prev combine done)

        // ---- load phase: 64 rows into splat-dup Xs ----
        for (int i = tid; i < 1024; i += 256) {
            int row = i >> 4, c4 = i & 15;
            int p = m0 + row;
            float4 v = make_float4(0.f, 0.f, 0.f, 0.f);
            if (p < M) {
                if (MODE == 0) {
                    v = __ldg(&((const float4*)X)[(size_t)p * 16 + c4]);
                    if (zbuf) zbuf[(size_t)p * 16 + c4] = make_float4(0.f, 0.f, 0.f, 0.f);
                } else {
                    int q = p / R, r = p - q * R;
                    float4 a = __ldg(&((const float4*)qe)[q * 16 + c4]);
                    float4 b = __ldg(&((const float4*)re)[r * 16 + c4]);
                    v = make_float4(a.x * b.x, a.y * b.y, a.z * b.z, a.w * b.w);
                }
            }
            u64* dst = &Xs[row * 64 + c4 * 4];
            dst[0] = pack2(v.x, v.x); dst[1] = pack2(v.y, v.y);
            dst[2] = pack2(v.z, v.z); dst[3] = pack2(v.w, v.w);
        }
        __syncthreads();

        // ---- mainloop: 16 rows per warp (stripe 4), 2-row interleave ----
        #pragma unroll
        for (int t = 0; t < 16; t += 2) {
            const int row0 = rg + t * 4;
            const int row1 = row0 + 4;
            const u64* x0 = &Xs[row0 * 64 + h * 32];
            const u64* x1 = &Xs[row1 * 64 + h * 32];
            u64 a0 = 0ull, a1 = 0ull;
            #pragma unroll
            for (int j = 0; j < 32; j += 2) {
                ulonglong2 p0 = *(const ulonglong2*)&x0[j];
                ulonglong2 p1 = *(const ulonglong2*)&x1[j];
                a0 = ffma2(p0.x, Wr[j],     a0);
                a1 = ffma2(p1.x, Wr[j],     a1);
                a0 = ffma2(p0.y, Wr[j + 1], a0);
                a1 = ffma2(p1.y, Wr[j + 1], a1);
            }
            Ps[(row0 * 2 + h) * 32 + lane] = a0;
            Ps[(row1 * 2 + h) * 32 + lane] = a1;
        }
        __syncthreads();

        // ---- combine k-halves + epilogue ----
        for (int i = tid; i < 2048; i += 256) {
            int row = i >> 5, l = i & 31;
            int p = m0 + row;
            if (p < M) {
                u64 s = addf32x2(Ps[(row * 2) * 32 + l], Ps[(row * 2 + 1) * 32 + l]);
                if (MODE == 0) {
                    if (bias) s = addf32x2(s, *(const u64*)&bias[2 * l]);
                } else {
                    int q = p / R, r = p - q * R;
                    s = addf32x2(s, __ldg((const u64*)&tR[r * 64 + 2 * l]));
                    s = addf32x2(s, __ldg((const u64*)&tQ[q * 64 + 2 * l]));
                }
                *(u64*)&out[(size_t)p * 64 + 2 * l] = s;
            }
        }
    }
}

// -----------------------------------------------------------------------------
// Edge kernel: half-warp (16 lanes) per edge, float4 per lane.
// -----------------------------------------------------------------------------
__global__ __launch_bounds__(256)
void edge_kernel(const int* __restrict__ edges,
                 const float* __restrict__ hidden,
                 const float* __restrict__ rela,
                 const float* __restrict__ wa_W,
                 const float* __restrict__ wa_b,
                 const float* __restrict__ tS,
                 const float* __restrict__ tQR,
                 float* __restrict__ agg,
                 float* __restrict__ alpha_out,
                 int E, int R)
{
    const int t = blockIdx.x * 256 + threadIdx.x;
    const int e = t >> 4;
    if (e >= E) return;
    const int sl = t & 15;

    const int* er = edges + (size_t)e * 6;
    const int q = __ldg(er + 0);
    const int r = __ldg(er + 2);
    const int s = __ldg(er + 4);
    const int o = __ldg(er + 5);

    float4 g   = __ldg(&((const float4*)tS)[(size_t)s * 16 + sl]);
    float4 p2  = __ldg(&((const float4*)tQR)[((size_t)q * R + r) * 16 + sl]);
    float4 hs  = __ldg(&((const float4*)hidden)[(size_t)s * 16 + sl]);
    float4 hr  = __ldg(&((const float4*)rela)[(size_t)r * 16 + sl]);
    float4 wa  = __ldg(&((const float4*)wa_W)[sl]);

    float px = fmaxf(g.x + p2.x, 0.f);
    float py = fmaxf(g.y + p2.y, 0.f);
    float pz = fmaxf(g.z + p2.z, 0.f);
    float pw = fmaxf(g.w + p2.w, 0.f);

    float part = fmaf(px, wa.x, fmaf(py, wa.y, fmaf(pz, wa.z, pw * wa.w)));
    #pragma unroll
    for (int off = 8; off; off >>= 1)
        part += __shfl_xor_sync(0xffffffffu, part, off);

    float alpha = 1.0f / (1.0f + __expf(-(part + __ldg(wa_b))));
    if (sl == 0) alpha_out[e] = alpha;

    float4 m;
    m.x = alpha * hs.x * hr.x;
    m.y = alpha * hs.y * hr.y;
    m.z = alpha * hs.z * hr.z;
    m.w = alpha * hs.w * hr.w;

    float* dst = &agg[(size_t)o * 64 + sl * 4];
    asm volatile("red.global.add.v4.f32 [%0], {%1, %2, %3, %4};"
                 :: "l"(dst), "f"(m.x), "f"(m.y), "f"(m.z), "f"(m.w) : "memory");
}

// -----------------------------------------------------------------------------
extern "C" void kernel_launch(void* const* d_in, const int* in_sizes, int n_in,
                              void* d_out, int out_size)
{
    const float* q_emb  = (const float*)d_in[1];
    const float* rela   = (const float*)d_in[2];
    const float* hidden = (const float*)d_in[3];
    const int*   edges  = (const int*)d_in[4];
    const float* Ws_W   = (const float*)d_in[6];
    const float* Ws_b   = (const float*)d_in[7];
    const float* Wr_W   = (const float*)d_in[8];
    const float* Wq_W   = (const float*)d_in[9];
    const float* Wqr_W  = (const float*)d_in[10];
    const float* wa_W   = (const float*)d_in[11];
    const float* wa_b   = (const float*)d_in[12];
    const float* Wh_W   = (const float*)d_in[13];

    const int Q = in_sizes[0];
    const int R = in_sizes[2] / 64;
    const int N = in_sizes[3] / 64;
    const int E = in_sizes[4] / 6;

    float* out = (float*)d_out;
    float* alpha_out = out + (size_t)N * 64;

    float *tS, *tR, *tQ, *tQR, *agg;
    cudaGetSymbolAddress((void**)&tS,  g_tableS);
    cudaGetSymbolAddress((void**)&tR,  g_tableR);
    cudaGetSymbolAddress((void**)&tQ,  g_tableQ);
    cudaGetSymbolAddress((void**)&tQR, g_tableQR);
    cudaGetSymbolAddress((void**)&agg, g_agg);

    const int SMEM = (64 * 32 + 64 * 64 + 64 * 64) * 8;   // 80 KB
    cudaFuncSetAttribute(gemm64<0>, cudaFuncAttributeMaxDynamicSharedMemorySize, SMEM);
    cudaFuncSetAttribute(gemm64<1>, cudaFuncAttributeMaxDynamicSharedMemorySize, SMEM);

    auto grid_for = [](int M) {
        int b = (M + 63) / 64;
        return b < 296 ? b : 296;   // persistent: 2 CTAs x 148 SMs
    };

    // Small tables first (inputs to the QR fold)
    gemm64<0><<<grid_for(R), 256, SMEM>>>(rela,  nullptr, nullptr, Wr_W, nullptr,
                                          nullptr, nullptr, tR, R, R, nullptr);
    gemm64<0><<<grid_for(Q), 256, SMEM>>>(q_emb, nullptr, nullptr, Wq_W, nullptr,
                                          nullptr, nullptr, tQ, Q, R, nullptr);

    // Big precomputes (tS pass also zeroes agg rows)
    gemm64<0><<<grid_for(N), 256, SMEM>>>(hidden, nullptr, nullptr, Ws_W, Ws_b,
                                          nullptr, nullptr, tS, N, R, (float4*)agg);
    gemm64<1><<<grid_for(Q * R), 256, SMEM>>>(nullptr, q_emb, rela, Wqr_W, nullptr,
                                              tR, tQ, tQR, Q * R, R, nullptr);

    // Per-edge gather/gate/scatter (half-warp per edge)
    edge_kernel<<<(E * 16 + 255) / 256, 256>>>(edges, hidden, rela, wa_W, wa_b,
                                               tS, tQR, agg, alpha_out, E, R);

    // Final projection: hidden_new = agg @ Wh^T
    gemm64<0><<<grid_for(N), 256, SMEM>>>(agg, nullptr, nullptr, Wh_W, nullptr,
                                          nullptr, nullptr, out, N, R, nullptr);
}

// round 7
// speedup vs baseline: 1.5228x; 1.3381x over previous
#include <cuda_runtime.h>
#include <cuda_bf16.h>
#include <math.h>

typedef unsigned int u32;
typedef unsigned long long u64;

// Fixed problem shape
#define NMAX 100000
#define QMAX 256
#define RMAX 401

// Scratch (device globals — no allocation allowed)
__device__ float g_tableS[NMAX * 64];
__device__ float g_tableR[RMAX * 64];
__device__ float g_tableQ[QMAX * 64];
__device__ float g_tableQR[QMAX * RMAX * 64];
__device__ float g_agg[NMAX * 64];

// ---- helpers ----
__device__ __forceinline__ u32 pack_bf2(float lo, float hi) {
    __nv_bfloat162 t = __floats2bfloat162_rn(lo, hi);   // .x=lo (low 16), .y=hi
    return *(u32*)&t;
}
__device__ __forceinline__ void split_bf(float x, float& hi, float& lo) {
    __nv_bfloat16 h = __float2bfloat16_rn(x);
    hi = __bfloat162float(h);
    lo = x - hi;
}

// mma.sync m16n8k16 bf16, fp32 accumulate
__device__ __forceinline__ void mma16816(float c[4], const u32 a[4], u32 b0, u32 b1) {
    asm volatile(
        "mma.sync.aligned.m16n8k16.row.col.f32.bf16.bf16.f32 "
        "{%0,%1,%2,%3}, {%4,%5,%6,%7}, {%8,%9}, {%0,%1,%2,%3};"
        : "+f"(c[0]), "+f"(c[1]), "+f"(c[2]), "+f"(c[3])
        : "r"(a[0]), "r"(a[1]), "r"(a[2]), "r"(a[3]), "r"(b0), "r"(b1));
}

__device__ __forceinline__ void ldmatrix_x4(u32 a[4], u32 addr) {
    asm volatile("ldmatrix.sync.aligned.m8n8.x4.shared.b16 {%0,%1,%2,%3}, [%4];"
                 : "=r"(a[0]), "=r"(a[1]), "=r"(a[2]), "=r"(a[3]) : "r"(addr));
}

// -----------------------------------------------------------------------------
// Tensor-core 64x64 NT GEMM with bf16 hi/lo split (3-MMA emulated fp32).
//   out[m,a] = sum_d X[m,d] * W[a,d]  (+ epilogue)
// One 128-row tile per CTA, 256 threads = 8 warps:
//   warp: colgroup cg = w&3 (16 cols = 2 n8-tiles), rowgroup rg = w>>2 (64 rows
//   = 4 m16-tiles). W frags in registers (built once), X staged as swizzled
//   bf16 hi/lo planes in smem; mainloop = ldmatrix.x4 + HMMA only.
// MODE 0: X from gmem; optional bias; optional zbuf zeroing (fused agg clear).
// MODE 1: X row p=(q,r) = q_emb[q]⊙rela[r]; epilogue adds tR[r]+tQ[q].
// -----------------------------------------------------------------------------
template<int MODE>
__global__ __launch_bounds__(256, 2)
void gemm_tc(const float* __restrict__ X,
             const float* __restrict__ qe,
             const float* __restrict__ re,
             const float* __restrict__ W,
             const float* __restrict__ bias,
             const float* __restrict__ tR,
             const float* __restrict__ tQ,
             float* __restrict__ out, int M, int R,
             float4* __restrict__ zbuf)
{
    __shared__ unsigned char sX[2 * 128 * 128];   // hi plane | lo plane (16 KB each)
    const int tid  = threadIdx.x;
    const int lane = tid & 31;
    const int w    = tid >> 5;
    const int cg   = w & 3;
    const int rg   = w >> 2;
    const int m0b  = blockIdx.x * 128;

    // ---- W fragments (hi/lo) in registers: [nt][ks][reg] ----
    u32 Bhi[2][4][2], Blo[2][4][2];
    {
        const int n_base = cg * 16 + (lane >> 2);
        const int k_base = (lane & 3) * 2;
        #pragma unroll
        for (int nt = 0; nt < 2; nt++) {
            #pragma unroll
            for (int ks = 0; ks < 4; ks++) {
                const float* wr = &W[(n_base + nt * 8) * 64 + ks * 16 + k_base];
                float w0 = __ldg(wr),     w1 = __ldg(wr + 1);
                float w2 = __ldg(wr + 8), w3 = __ldg(wr + 9);
                float h0, l0, h1, l1, h2, l2, h3, l3;
                split_bf(w0, h0, l0); split_bf(w1, h1, l1);
                split_bf(w2, h2, l2); split_bf(w3, h3, l3);
                Bhi[nt][ks][0] = pack_bf2(h0, h1); Bhi[nt][ks][1] = pack_bf2(h2, h3);
                Blo[nt][ks][0] = pack_bf2(l0, l1); Blo[nt][ks][1] = pack_bf2(l2, l3);
            }
        }
    }

    // ---- stage X tile: fp32 -> swizzled bf16 hi/lo planes ----
    // Plane row = 64 bf16 = 128 B. Swizzle: byte ^= (row&7)<<4 (16B granules).
    for (int i = tid; i < 128 * 16; i += 256) {
        int row = i >> 4, c4 = i & 15;
        int p = m0b + row;
        float4 v = make_float4(0.f, 0.f, 0.f, 0.f);
        if (p < M) {
            if (MODE == 0) {
                v = __ldg(&((const float4*)X)[(size_t)p * 16 + c4]);
                if (zbuf) zbuf[(size_t)p * 16 + c4] = make_float4(0.f, 0.f, 0.f, 0.f);
            } else {
                int q = p / R, r = p - q * R;
                float4 a = __ldg(&((const float4*)qe)[q * 16 + c4]);
                float4 b = __ldg(&((const float4*)re)[r * 16 + c4]);
                v = make_float4(a.x * b.x, a.y * b.y, a.z * b.z, a.w * b.w);
            }
        }
        float hx, lx, hy, ly, hz, lz, hw, lw;
        split_bf(v.x, hx, lx); split_bf(v.y, hy, ly);
        split_bf(v.z, hz, lz); split_bf(v.w, hw, lw);
        u32 off = (u32)(row * 128 + ((c4 * 8) ^ ((row & 7) << 4)));
        *(uint2*)(sX + off)         = make_uint2(pack_bf2(hx, hy), pack_bf2(hz, hw));
        *(uint2*)(sX + 16384 + off) = make_uint2(pack_bf2(lx, ly), pack_bf2(lz, lw));
    }
    __syncthreads();

    const u32 sbase = (u32)__cvta_generic_to_shared(sX);
    // ldmatrix lane address components
    const int mi = lane >> 3, lr = lane & 7;
    const int row_off = (mi & 1) * 8 + lr;              // within m-tile
    const int kb_off  = (mi >> 1) * 16;                 // byte col within k-step

    // ---- per m-tile: ldmatrix + 3-way split MMA ----
    #pragma unroll
    for (int mt = 0; mt < 4; mt++) {
        const int mrow = rg * 64 + mt * 16;             // block-relative
        float acc[2][4] = {{0.f,0.f,0.f,0.f},{0.f,0.f,0.f,0.f}};

        #pragma unroll
        for (int ks = 0; ks < 4; ks++) {
            const int row = mrow + row_off;
            const u32 byte = (u32)(row * 128 + ((ks * 32 + kb_off) ^ ((row & 7) << 4)));
            u32 Ahi[4], Alo[4];
            ldmatrix_x4(Ahi, sbase + byte);
            ldmatrix_x4(Alo, sbase + 16384 + byte);
            #pragma unroll
            for (int nt = 0; nt < 2; nt++) {
                mma16816(acc[nt], Ahi, Bhi[nt][ks][0], Bhi[nt][ks][1]);
                mma16816(acc[nt], Ahi, Blo[nt][ks][0], Blo[nt][ks][1]);
                mma16816(acc[nt], Alo, Bhi[nt][ks][0], Bhi[nt][ks][1]);
            }
        }

        // ---- epilogue ----
        const int r0 = m0b + mrow + (lane >> 2);        // global row (c0,c1)
        const int r1 = r0 + 8;                          // global row (c2,c3)
        #pragma unroll
        for (int nt = 0; nt < 2; nt++) {
            const int col = cg * 16 + nt * 8 + (lane & 3) * 2;
            float2 e0 = make_float2(acc[nt][0], acc[nt][1]);
            float2 e1 = make_float2(acc[nt][2], acc[nt][3]);
            if (MODE == 0) {
                if (bias) {
                    float2 bv = *(const float2*)&bias[col];
                    e0.x += bv.x; e0.y += bv.y; e1.x += bv.x; e1.y += bv.y;
                }
            } else {
                if (r0 < M) {
                    int q = r0 / R, r = r0 - q * R;
                    float2 t1 = __ldg((const float2*)&tR[r * 64 + col]);
                    float2 t2 = __ldg((const float2*)&tQ[q * 64 + col]);
                    e0.x += t1.x + t2.x; e0.y += t1.y + t2.y;
                }
                if (r1 < M) {
                    int q = r1 / R, r = r1 - q * R;
                    float2 t1 = __ldg((const float2*)&tR[r * 64 + col]);
                    float2 t2 = __ldg((const float2*)&tQ[q * 64 + col]);
                    e1.x += t1.x + t2.x; e1.y += t1.y + t2.y;
                }
            }
            if (r0 < M) *(float2*)&out[(size_t)r0 * 64 + col] = e0;
            if (r1 < M) *(float2*)&out[(size_t)r1 * 64 + col] = e1;
        }
    }
}

// -----------------------------------------------------------------------------
// Edge kernel: half-warp (16 lanes) per edge, float4 per lane.
// -----------------------------------------------------------------------------
__global__ __launch_bounds__(256)
void edge_kernel(const int* __restrict__ edges,
                 const float* __restrict__ hidden,
                 const float* __restrict__ rela,
                 const float* __restrict__ wa_W,
                 const float* __restrict__ wa_b,
                 const float* __restrict__ tS,
                 const float* __restrict__ tQR,
                 float* __restrict__ agg,
                 float* __restrict__ alpha_out,
                 int E, int R)
{
    const int t = blockIdx.x * 256 + threadIdx.x;
    const int e = t >> 4;
    if (e >= E) return;
    const int sl = t & 15;

    const int* er = edges + (size_t)e * 6;
    const int q = __ldg(er + 0);
    const int r = __ldg(er + 2);
    const int s = __ldg(er + 4);
    const int o = __ldg(er + 5);

    float4 g   = __ldg(&((const float4*)tS)[(size_t)s * 16 + sl]);
    float4 p2  = __ldg(&((const float4*)tQR)[((size_t)q * R + r) * 16 + sl]);
    float4 hs  = __ldg(&((const float4*)hidden)[(size_t)s * 16 + sl]);
    float4 hr  = __ldg(&((const float4*)rela)[(size_t)r * 16 + sl]);
    float4 wa  = __ldg(&((const float4*)wa_W)[sl]);

    float px = fmaxf(g.x + p2.x, 0.f);
    float py = fmaxf(g.y + p2.y, 0.f);
    float pz = fmaxf(g.z + p2.z, 0.f);
    float pw = fmaxf(g.w + p2.w, 0.f);

    float part = fmaf(px, wa.x, fmaf(py, wa.y, fmaf(pz, wa.z, pw * wa.w)));
    #pragma unroll
    for (int off = 8; off; off >>= 1)
        part += __shfl_xor_sync(0xffffffffu, part, off);

    float alpha = 1.0f / (1.0f + __expf(-(part + __ldg(wa_b))));
    if (sl == 0) alpha_out[e] = alpha;

    float4 m;
    m.x = alpha * hs.x * hr.x;
    m.y = alpha * hs.y * hr.y;
    m.z = alpha * hs.z * hr.z;
    m.w = alpha * hs.w * hr.w;

    float* dst = &agg[(size_t)o * 64 + sl * 4];
    asm volatile("red.global.add.v4.f32 [%0], {%1, %2, %3, %4};"
                 :: "l"(dst), "f"(m.x), "f"(m.y), "f"(m.z), "f"(m.w) : "memory");
}

// -----------------------------------------------------------------------------
extern "C" void kernel_launch(void* const* d_in, const int* in_sizes, int n_in,
                              void* d_out, int out_size)
{
    const float* q_emb  = (const float*)d_in[1];
    const float* rela   = (const float*)d_in[2];
    const float* hidden = (const float*)d_in[3];
    const int*   edges  = (const int*)d_in[4];
    const float* Ws_W   = (const float*)d_in[6];
    const float* Ws_b   = (const float*)d_in[7];
    const float* Wr_W   = (const float*)d_in[8];
    const float* Wq_W   = (const float*)d_in[9];
    const float* Wqr_W  = (const float*)d_in[10];
    const float* wa_W   = (const float*)d_in[11];
    const float* wa_b   = (const float*)d_in[12];
    const float* Wh_W   = (const float*)d_in[13];

    const int Q = in_sizes[0];
    const int R = in_sizes[2] / 64;
    const int N = in_sizes[3] / 64;
    const int E = in_sizes[4] / 6;

    float* out = (float*)d_out;
    float* alpha_out = out + (size_t)N * 64;

    float *tS, *tR, *tQ, *tQR, *agg;
    cudaGetSymbolAddress((void**)&tS,  g_tableS);
    cudaGetSymbolAddress((void**)&tR,  g_tableR);
    cudaGetSymbolAddress((void**)&tQ,  g_tableQ);
    cudaGetSymbolAddress((void**)&tQR, g_tableQR);
    cudaGetSymbolAddress((void**)&agg, g_agg);

    auto blocks = [](int M) { return (M + 127) / 128; };

    // Small tables first (inputs to the QR fold)
    gemm_tc<0><<<blocks(R), 256>>>(rela,  nullptr, nullptr, Wr_W, nullptr,
                                   nullptr, nullptr, tR, R, R, nullptr);
    gemm_tc<0><<<blocks(Q), 256>>>(q_emb, nullptr, nullptr, Wq_W, nullptr,
                                   nullptr, nullptr, tQ, Q, R, nullptr);

    // Big precomputes (tS pass also zeroes agg rows)
    gemm_tc<0><<<blocks(N), 256>>>(hidden, nullptr, nullptr, Ws_W, Ws_b,
                                   nullptr, nullptr, tS, N, R, (float4*)agg);
    gemm_tc<1><<<blocks(Q * R), 256>>>(nullptr, q_emb, rela, Wqr_W, nullptr,
                                       tR, tQ, tQR, Q * R, R, nullptr);

    // Per-edge gather/gate/scatter (half-warp per edge)
    edge_kernel<<<(E * 16 + 255) / 256, 256>>>(edges, hidden, rela, wa_W, wa_b,
                                               tS, tQR, agg, alpha_out, E, R);

    // Final projection: hidden_new = agg @ Wh^T
    gemm_tc<0><<<blocks(N), 256>>>(agg, nullptr, nullptr, Wh_W, nullptr,
                                   nullptr, nullptr, out, N, R, nullptr);
}

// round 8
// speedup vs baseline: 2.0224x; 1.3280x over previous
#include <cuda_runtime.h>
#include <cuda_bf16.h>
#include <math.h>

typedef unsigned int u32;
typedef unsigned long long u64;

// Fixed problem shape
#define NMAX 100000
#define QMAX 256
#define RMAX 401

// Scratch (device globals — no allocation allowed)
__device__ float g_tableS[NMAX * 64];
__device__ float g_tableR[RMAX * 64];
__device__ float g_tableQ[QMAX * 64];
__device__ float g_tableQR[QMAX * RMAX * 64];
__device__ float g_agg[NMAX * 64];

// ---- helpers ----
__device__ __forceinline__ u32 pack_bf2(float lo, float hi) {
    __nv_bfloat162 t = __floats2bfloat162_rn(lo, hi);   // .x=lo (low 16), .y=hi
    return *(u32*)&t;
}
__device__ __forceinline__ void split_bf(float x, float& hi, float& lo) {
    __nv_bfloat16 h = __float2bfloat16_rn(x);
    hi = __bfloat162float(h);
    lo = x - hi;
}
__device__ __forceinline__ u32 prmt_hi16(u32 a, u32 b) {
    u32 d;
    asm("prmt.b32 %0, %1, %2, 0x7632;" : "=r"(d) : "r"(a), "r"(b));
    return d;
}
// truncation split of 2 floats -> bf16x2 hi-pack + lo-pack (cheap: 6 simple ops)
__device__ __forceinline__ void split2(float x0, float x1, u32& hp, u32& lp) {
    u32 b0 = __float_as_uint(x0), b1 = __float_as_uint(x1);
    hp = prmt_hi16(b0, b1);
    float l0 = x0 - __uint_as_float(b0 & 0xFFFF0000u);
    float l1 = x1 - __uint_as_float(b1 & 0xFFFF0000u);
    lp = prmt_hi16(__float_as_uint(l0), __float_as_uint(l1));
}

// mma.sync m16n8k16 bf16, fp32 accumulate
__device__ __forceinline__ void mma16816(float c[4], const u32 a[4], u32 b0, u32 b1) {
    asm volatile(
        "mma.sync.aligned.m16n8k16.row.col.f32.bf16.bf16.f32 "
        "{%0,%1,%2,%3}, {%4,%5,%6,%7}, {%8,%9}, {%0,%1,%2,%3};"
        : "+f"(c[0]), "+f"(c[1]), "+f"(c[2]), "+f"(c[3])
        : "r"(a[0]), "r"(a[1]), "r"(a[2]), "r"(a[3]), "r"(b0), "r"(b1));
}
__device__ __forceinline__ void ldmatrix_x4(u32 a[4], u32 addr) {
    asm volatile("ldmatrix.sync.aligned.m8n8.x4.shared.b16 {%0,%1,%2,%3}, [%4];"
                 : "=r"(a[0]), "=r"(a[1]), "=r"(a[2]), "=r"(a[3]) : "r"(addr));
}

// -----------------------------------------------------------------------------
// Persistent, double-buffered tensor-core 64x64 NT GEMM (bf16 hi/lo, 3 MMAs).
//   out[m,a] = sum_d X[m,d] * W[a,d]  (+ epilogue)
// Pipeline per iteration: LDG(tile t+1) -> MMA(tile t) -> cvt+STS(t+1) -> sync.
// MODE 0: X from gmem; optional bias; optional zbuf zeroing (fused agg clear).
// MODE 1: X row p=(q,r) = q_emb[q]⊙rela[r]; epilogue adds tR[r]+tQ[q].
// -----------------------------------------------------------------------------
template<int MODE>
__global__ __launch_bounds__(256, 2)
void gemm_tc(const float* __restrict__ X,
             const float* __restrict__ qe,
             const float* __restrict__ re,
             const float* __restrict__ W,
             const float* __restrict__ bias,
             const float* __restrict__ tR,
             const float* __restrict__ tQ,
             float* __restrict__ out, int M, int R,
             float4* __restrict__ zbuf, int tiles)
{
    extern __shared__ unsigned char sX[];   // [2 bufs][hi 16KB | lo 16KB] = 64 KB
    const int tid  = threadIdx.x;
    const int lane = tid & 31;
    const int w    = tid >> 5;
    const int cg   = w & 3;
    const int rg   = w >> 2;

    // ---- W fragments (hi/lo) in registers: built once per CTA ----
    u32 Bhi[2][4][2], Blo[2][4][2];
    {
        const int n_base = cg * 16 + (lane >> 2);
        const int k_base = (lane & 3) * 2;
        #pragma unroll
        for (int nt = 0; nt < 2; nt++) {
            #pragma unroll
            for (int ks = 0; ks < 4; ks++) {
                const float* wr = &W[(n_base + nt * 8) * 64 + ks * 16 + k_base];
                float w0 = __ldg(wr),     w1 = __ldg(wr + 1);
                float w2 = __ldg(wr + 8), w3 = __ldg(wr + 9);
                float h0, l0, h1, l1, h2, l2, h3, l3;
                split_bf(w0, h0, l0); split_bf(w1, h1, l1);
                split_bf(w2, h2, l2); split_bf(w3, h3, l3);
                Bhi[nt][ks][0] = pack_bf2(h0, h1); Bhi[nt][ks][1] = pack_bf2(h2, h3);
                Blo[nt][ks][0] = pack_bf2(l0, l1); Blo[nt][ks][1] = pack_bf2(l2, l3);
            }
        }
    }

    const u32 sb = (u32)__cvta_generic_to_shared(sX);
    const int mi = lane >> 3, lr = lane & 7;
    const int row_off = (mi & 1) * 8 + lr;
    const int kb_off  = (mi >> 1) * 16;
    const int srow = tid >> 4, sc4 = tid & 15;      // staging coords (stride 16 rows)

    // ---- staging helpers (inlined) ----
    auto stage_load = [&](int tile, float4 v[8]) {
        const int p0 = tile * 128 + srow;
        int q = 0, r = 0;
        if (MODE == 1) { q = p0 / R; r = p0 - q * R; }
        #pragma unroll
        for (int j = 0; j < 8; j++) {
            int p = p0 + j * 16;
            float4 t = make_float4(0.f, 0.f, 0.f, 0.f);
            if (p < M) {
                if (MODE == 0) {
                    t = __ldg(&((const float4*)X)[(size_t)p * 16 + sc4]);
                    if (zbuf) zbuf[(size_t)p * 16 + sc4] = make_float4(0.f, 0.f, 0.f, 0.f);
                } else {
                    float4 a = __ldg(&((const float4*)qe)[q * 16 + sc4]);
                    float4 b = __ldg(&((const float4*)re)[r * 16 + sc4]);
                    t = make_float4(a.x * b.x, a.y * b.y, a.z * b.z, a.w * b.w);
                }
            }
            v[j] = t;
            if (MODE == 1) { r += 16; if (r >= R) { r -= R; q++; } }
        }
    };
    auto stage_store = [&](const float4 v[8], int buf) {
        unsigned char* base = sX + buf * 32768;
        #pragma unroll
        for (int j = 0; j < 8; j++) {
            int row = srow + j * 16;
            u32 off = (u32)(row * 128 + ((sc4 * 8) ^ ((row & 7) << 4)));
            u32 h0, l0, h1, l1;
            split2(v[j].x, v[j].y, h0, l0);
            split2(v[j].z, v[j].w, h1, l1);
            *(uint2*)(base + off)         = make_uint2(h0, h1);
            *(uint2*)(base + 16384 + off) = make_uint2(l0, l1);
        }
    };

    auto mma_epilogue = [&](int buf, int m0b) {
        const u32 hi_base = sb + buf * 32768;
        // incremental (q,r) for the two output row streams (MODE 1)
        int q0 = 0, rr0 = 0, q1 = 0, rr1 = 0;
        if (MODE == 1) {
            int p0 = m0b + rg * 64 + (lane >> 2);
            q0 = p0 / R; rr0 = p0 - q0 * R;
            int p1 = p0 + 8;
            q1 = p1 / R; rr1 = p1 - q1 * R;
        }
        #pragma unroll
        for (int mt = 0; mt < 4; mt++) {
            const int mrow = rg * 64 + mt * 16;
            float acc[2][4] = {{0.f,0.f,0.f,0.f},{0.f,0.f,0.f,0.f}};
            #pragma unroll
            for (int ks = 0; ks < 4; ks++) {
                const int row = mrow + row_off;
                const u32 byte = (u32)(row * 128 + ((ks * 32 + kb_off) ^ ((row & 7) << 4)));
                u32 Ahi[4], Alo[4];
                ldmatrix_x4(Ahi, hi_base + byte);
                ldmatrix_x4(Alo, hi_base + 16384 + byte);
                #pragma unroll
                for (int nt = 0; nt < 2; nt++) {
                    mma16816(acc[nt], Ahi, Bhi[nt][ks][0], Bhi[nt][ks][1]);
                    mma16816(acc[nt], Ahi, Blo[nt][ks][0], Blo[nt][ks][1]);
                    mma16816(acc[nt], Alo, Bhi[nt][ks][0], Bhi[nt][ks][1]);
                }
            }
            const int r0 = m0b + mrow + (lane >> 2);
            const int r1 = r0 + 8;
            #pragma unroll
            for (int nt = 0; nt < 2; nt++) {
                const int col = cg * 16 + nt * 8 + (lane & 3) * 2;
                float2 e0 = make_float2(acc[nt][0], acc[nt][1]);
                float2 e1 = make_float2(acc[nt][2], acc[nt][3]);
                if (MODE == 0) {
                    if (bias) {
                        float2 bv = *(const float2*)&bias[col];
                        e0.x += bv.x; e0.y += bv.y; e1.x += bv.x; e1.y += bv.y;
                    }
                } else {
                    if (r0 < M) {
                        float2 t1 = __ldg((const float2*)&tR[rr0 * 64 + col]);
                        float2 t2 = __ldg((const float2*)&tQ[q0 * 64 + col]);
                        e0.x += t1.x + t2.x; e0.y += t1.y + t2.y;
                    }
                    if (r1 < M) {
                        float2 t1 = __ldg((const float2*)&tR[rr1 * 64 + col]);
                        float2 t2 = __ldg((const float2*)&tQ[q1 * 64 + col]);
                        e1.x += t1.x + t2.x; e1.y += t1.y + t2.y;
                    }
                }
                if (r0 < M) *(float2*)&out[(size_t)r0 * 64 + col] = e0;
                if (r1 < M) *(float2*)&out[(size_t)r1 * 64 + col] = e1;
            }
            if (MODE == 1) {
                rr0 += 16; if (rr0 >= R) { rr0 -= R; q0++; }
                rr1 += 16; if (rr1 >= R) { rr1 -= R; q1++; }
            }
        }
    };

    // ---- persistent pipelined loop ----
    int tile = blockIdx.x;
    {
        float4 v[8];
        stage_load(tile, v);
        stage_store(v, 0);
    }
    __syncthreads();
    int cur = 0;
    while (tile < tiles) {
        const int nxt = tile + gridDim.x;
        const bool have = (nxt < tiles);
        float4 v[8];
        if (have) stage_load(nxt, v);
        mma_epilogue(cur, tile * 128);
        if (have) stage_store(v, cur ^ 1);
        __syncthreads();
        cur ^= 1;
        tile = nxt;
    }
}

// -----------------------------------------------------------------------------
// Edge kernel: half-warp (16 lanes) per edge, float4 per lane.
// -----------------------------------------------------------------------------
__global__ __launch_bounds__(256)
void edge_kernel(const int* __restrict__ edges,
                 const float* __restrict__ hidden,
                 const float* __restrict__ rela,
                 const float* __restrict__ wa_W,
                 const float* __restrict__ wa_b,
                 const float* __restrict__ tS,
                 const float* __restrict__ tQR,
                 float* __restrict__ agg,
                 float* __restrict__ alpha_out,
                 int E, int R)
{
    const int t = blockIdx.x * 256 + threadIdx.x;
    const int e = t >> 4;
    if (e >= E) return;
    const int sl = t & 15;

    const int* er = edges + (size_t)e * 6;
    const int q = __ldg(er + 0);
    const int r = __ldg(er + 2);
    const int s = __ldg(er + 4);
    const int o = __ldg(er + 5);

    float4 g   = __ldg(&((const float4*)tS)[(size_t)s * 16 + sl]);
    float4 p2  = __ldg(&((const float4*)tQR)[((size_t)q * R + r) * 16 + sl]);
    float4 hs  = __ldg(&((const float4*)hidden)[(size_t)s * 16 + sl]);
    float4 hr  = __ldg(&((const float4*)rela)[(size_t)r * 16 + sl]);
    float4 wa  = __ldg(&((const float4*)wa_W)[sl]);

    float px = fmaxf(g.x + p2.x, 0.f);
    float py = fmaxf(g.y + p2.y, 0.f);
    float pz = fmaxf(g.z + p2.z, 0.f);
    float pw = fmaxf(g.w + p2.w, 0.f);

    float part = fmaf(px, wa.x, fmaf(py, wa.y, fmaf(pz, wa.z, pw * wa.w)));
    #pragma unroll
    for (int off = 8; off; off >>= 1)
        part += __shfl_xor_sync(0xffffffffu, part, off);

    float alpha = 1.0f / (1.0f + __expf(-(part + __ldg(wa_b))));
    if (sl == 0) alpha_out[e] = alpha;

    float4 m;
    m.x = alpha * hs.x * hr.x;
    m.y = alpha * hs.y * hr.y;
    m.z = alpha * hs.z * hr.z;
    m.w = alpha * hs.w * hr.w;

    float* dst = &agg[(size_t)o * 64 + sl * 4];
    asm volatile("red.global.add.v4.f32 [%0], {%1, %2, %3, %4};"
                 :: "l"(dst), "f"(m.x), "f"(m.y), "f"(m.z), "f"(m.w) : "memory");
}

// -----------------------------------------------------------------------------
extern "C" void kernel_launch(void* const* d_in, const int* in_sizes, int n_in,
                              void* d_out, int out_size)
{
    const float* q_emb  = (const float*)d_in[1];
    const float* rela   = (const float*)d_in[2];
    const float* hidden = (const float*)d_in[3];
    const int*   edges  = (const int*)d_in[4];
    const float* Ws_W   = (const float*)d_in[6];
    const float* Ws_b   = (const float*)d_in[7];
    const float* Wr_W   = (const float*)d_in[8];
    const float* Wq_W   = (const float*)d_in[9];
    const float* Wqr_W  = (const float*)d_in[10];
    const float* wa_W   = (const float*)d_in[11];
    const float* wa_b   = (const float*)d_in[12];
    const float* Wh_W   = (const float*)d_in[13];

    const int Q = in_sizes[0];
    const int R = in_sizes[2] / 64;
    const int N = in_sizes[3] / 64;
    const int E = in_sizes[4] / 6;

    float* out = (float*)d_out;
    float* alpha_out = out + (size_t)N * 64;

    float *tS, *tR, *tQ, *tQR, *agg;
    cudaGetSymbolAddress((void**)&tS,  g_tableS);
    cudaGetSymbolAddress((void**)&tR,  g_tableR);
    cudaGetSymbolAddress((void**)&tQ,  g_tableQ);
    cudaGetSymbolAddress((void**)&tQR, g_tableQR);
    cudaGetSymbolAddress((void**)&agg, g_agg);

    const int SMEM = 65536;   // 2 x (hi 16KB + lo 16KB)
    cudaFuncSetAttribute(gemm_tc<0>, cudaFuncAttributeMaxDynamicSharedMemorySize, SMEM);
    cudaFuncSetAttribute(gemm_tc<1>, cudaFuncAttributeMaxDynamicSharedMemorySize, SMEM);

    auto tiles_of = [](int M) { return (M + 127) / 128; };
    auto grid_of  = [&](int M) { int t = tiles_of(M); return t < 296 ? t : 296; };

    // Small tables first (inputs to the QR fold)
    gemm_tc<0><<<grid_of(R), 256, SMEM>>>(rela,  nullptr, nullptr, Wr_W, nullptr,
                                          nullptr, nullptr, tR, R, R, nullptr, tiles_of(R));
    gemm_tc<0><<<grid_of(Q), 256, SMEM>>>(q_emb, nullptr, nullptr, Wq_W, nullptr,
                                          nullptr, nullptr, tQ, Q, R, nullptr, tiles_of(Q));

    // Big precomputes (tS pass also zeroes agg rows)
    gemm_tc<0><<<grid_of(N), 256, SMEM>>>(hidden, nullptr, nullptr, Ws_W, Ws_b,
                                          nullptr, nullptr, tS, N, R, (float4*)agg, tiles_of(N));
    gemm_tc<1><<<grid_of(Q * R), 256, SMEM>>>(nullptr, q_emb, rela, Wqr_W, nullptr,
                                              tR, tQ, tQR, Q * R, R, nullptr, tiles_of(Q * R));

    // Per-edge gather/gate/scatter (half-warp per edge)
    edge_kernel<<<(E * 16 + 255) / 256, 256>>>(edges, hidden, rela, wa_W, wa_b,
                                               tS, tQR, agg, alpha_out, E, R);

    // Final projection: hidden_new = agg @ Wh^T
    gemm_tc<0><<<grid_of(N), 256, SMEM>>>(agg, nullptr, nullptr, Wh_W, nullptr,
                                          nullptr, nullptr, out, N, R, nullptr, tiles_of(N));
}

// round 10
// speedup vs baseline: 2.1361x; 1.0563x over previous
#include <cuda_runtime.h>
#include <cuda_bf16.h>

typedef unsigned int u32;
typedef unsigned long long u64;

// Fixed problem shape
#define NMAX 100000
#define QMAX 256
#define RMAX 401

// Scratch (device globals — no allocation allowed)
__device__ float g_tableS[NMAX * 64];
__device__ float g_tableR[RMAX * 64];
__device__ float g_tableQ[QMAX * 64];
__device__ float g_tableQR[QMAX * RMAX * 64];
__device__ float g_agg[NMAX * 64];

// ---- helpers ----
__device__ __forceinline__ u32 pack_bf2(float lo, float hi) {
    __nv_bfloat162 t = __floats2bfloat162_rn(lo, hi);
    return *(u32*)&t;
}
__device__ __forceinline__ void split_bf(float x, float& hi, float& lo) {
    __nv_bfloat16 h = __float2bfloat16_rn(x);
    hi = __bfloat162float(h);
    lo = x - hi;
}
__device__ __forceinline__ u32 prmt_hi16(u32 a, u32 b) {
    u32 d;
    asm("prmt.b32 %0, %1, %2, 0x7632;" : "=r"(d) : "r"(a), "r"(b));
    return d;
}
// truncation split of 2 floats -> bf16x2 hi-pack + lo-pack
__device__ __forceinline__ void split2(float x0, float x1, u32& hp, u32& lp) {
    u32 b0 = __float_as_uint(x0), b1 = __float_as_uint(x1);
    hp = prmt_hi16(b0, b1);
    float l0 = x0 - __uint_as_float(b0 & 0xFFFF0000u);
    float l1 = x1 - __uint_as_float(b1 & 0xFFFF0000u);
    lp = prmt_hi16(__float_as_uint(l0), __float_as_uint(l1));
}

// mma.sync m16n8k16 bf16, fp32 accumulate
__device__ __forceinline__ void mma16816(float c[4], const u32 a[4], u32 b0, u32 b1) {
    asm volatile(
        "mma.sync.aligned.m16n8k16.row.col.f32.bf16.bf16.f32 "
        "{%0,%1,%2,%3}, {%4,%5,%6,%7}, {%8,%9}, {%0,%1,%2,%3};"
        : "+f"(c[0]), "+f"(c[1]), "+f"(c[2]), "+f"(c[3])
        : "r"(a[0]), "r"(a[1]), "r"(a[2]), "r"(a[3]), "r"(b0), "r"(b1));
}
__device__ __forceinline__ void ldmatrix_x4(u32 a[4], u32 addr) {
    asm volatile("ldmatrix.sync.aligned.m8n8.x4.shared.b16 {%0,%1,%2,%3}, [%4];"
                 : "=r"(a[0]), "=r"(a[1]), "=r"(a[2]), "=r"(a[3]) : "r"(addr));
}

// -----------------------------------------------------------------------------
// Persistent, double-buffered tensor-core 64x64 NT GEMM (bf16 hi/lo, 3 MMAs).
// Split accumulators: accA = hi*hi chain, accB = cross-term chain (2x ILP).
// MODE 0: X from gmem; optional bias; optional zbuf zeroing (fused agg clear).
// MODE 1: X row p=(q,r) = q_emb[q]*rela[r]; epilogue adds tR[r]+tQ[q].
// -----------------------------------------------------------------------------
template<int MODE>
__device__ __forceinline__
void gemm_body(const float* __restrict__ X,
               const float* __restrict__ qe,
               const float* __restrict__ re,
               const float* __restrict__ W,
               const float* __restrict__ bias,
               const float* __restrict__ tR,
               const float* __restrict__ tQ,
               float* __restrict__ out, int M, int R,
               float4* __restrict__ zbuf, int tiles,
               int tile0, int stride)
{
    extern __shared__ unsigned char sX[];   // [2 bufs][hi 16KB | lo 16KB] = 64 KB
    const int tid  = threadIdx.x;
    const int lane = tid & 31;
    const int w    = tid >> 5;
    const int cg   = w & 3;
    const int rg   = w >> 2;

    // ---- W fragments (hi/lo) in registers: built once per CTA ----
    u32 Bhi[2][4][2], Blo[2][4][2];
    {
        const int n_base = cg * 16 + (lane >> 2);
        const int k_base = (lane & 3) * 2;
        #pragma unroll
        for (int nt = 0; nt < 2; nt++) {
            #pragma unroll
            for (int ks = 0; ks < 4; ks++) {
                const float* wr = &W[(n_base + nt * 8) * 64 + ks * 16 + k_base];
                float w0 = __ldg(wr),     w1 = __ldg(wr + 1);
                float w2 = __ldg(wr + 8), w3 = __ldg(wr + 9);
                float h0, l0, h1, l1, h2, l2, h3, l3;
                split_bf(w0, h0, l0); split_bf(w1, h1, l1);
                split_bf(w2, h2, l2); split_bf(w3, h3, l3);
                Bhi[nt][ks][0] = pack_bf2(h0, h1); Bhi[nt][ks][1] = pack_bf2(h2, h3);
                Blo[nt][ks][0] = pack_bf2(l0, l1); Blo[nt][ks][1] = pack_bf2(l2, l3);
            }
        }
    }

    const u32 sb = (u32)__cvta_generic_to_shared(sX);
    const int mi = lane >> 3, lr = lane & 7;
    const int row_off = (mi & 1) * 8 + lr;
    const int kb_off  = (mi >> 1) * 16;
    const int srow = tid >> 4, sc4 = tid & 15;

    // ---- staging helpers ----
    auto stage_load = [&](int tile, float4 v[8]) {
        const int p0 = tile * 128 + srow;
        int q = 0, r = 0;
        if (MODE == 1) { q = p0 / R; r = p0 - q * R; }
        #pragma unroll
        for (int j = 0; j < 8; j++) {
            int p = p0 + j * 16;
            float4 t = make_float4(0.f, 0.f, 0.f, 0.f);
            if (p < M) {
                if (MODE == 0) {
                    t = __ldg(&((const float4*)X)[(size_t)p * 16 + sc4]);
                    if (zbuf) zbuf[(size_t)p * 16 + sc4] = make_float4(0.f, 0.f, 0.f, 0.f);
                } else {
                    float4 a = __ldg(&((const float4*)qe)[q * 16 + sc4]);
                    float4 b = __ldg(&((const float4*)re)[r * 16 + sc4]);
                    t = make_float4(a.x * b.x, a.y * b.y, a.z * b.z, a.w * b.w);
                }
            }
            v[j] = t;
            if (MODE == 1) { r += 16; if (r >= R) { r -= R; q++; } }
        }
    };
    auto stage_store = [&](const float4 v[8], int buf) {
        unsigned char* base = sX + buf * 32768;
        #pragma unroll
        for (int j = 0; j < 8; j++) {
            int row = srow + j * 16;
            u32 off = (u32)(row * 128 + ((sc4 * 8) ^ ((row & 7) << 4)));
            u32 h0, l0, h1, l1;
            split2(v[j].x, v[j].y, h0, l0);
            split2(v[j].z, v[j].w, h1, l1);
            *(uint2*)(base + off)         = make_uint2(h0, h1);
            *(uint2*)(base + 16384 + off) = make_uint2(l0, l1);
        }
    };

    auto mma_epilogue = [&](int buf, int m0b) {
        const u32 hi_base = sb + buf * 32768;
        int q0 = 0, rr0 = 0, q1 = 0, rr1 = 0;
        if (MODE == 1) {
            int p0 = m0b + rg * 64 + (lane >> 2);
            q0 = p0 / R; rr0 = p0 - q0 * R;
            int p1 = p0 + 8;
            q1 = p1 / R; rr1 = p1 - q1 * R;
        }
        #pragma unroll
        for (int mt = 0; mt < 4; mt++) {
            const int mrow = rg * 64 + mt * 16;
            // split accumulators: accA = hi*hi, accB = cross terms
            float accA[2][4] = {{0.f,0.f,0.f,0.f},{0.f,0.f,0.f,0.f}};
            float accB[2][4] = {{0.f,0.f,0.f,0.f},{0.f,0.f,0.f,0.f}};
            #pragma unroll
            for (int ks = 0; ks < 4; ks++) {
                const int row = mrow + row_off;
                const u32 byte = (u32)(row * 128 + ((ks * 32 + kb_off) ^ ((row & 7) << 4)));
                u32 Ahi[4], Alo[4];
                ldmatrix_x4(Ahi, hi_base + byte);
                ldmatrix_x4(Alo, hi_base + 16384 + byte);
                #pragma unroll
                for (int nt = 0; nt < 2; nt++) {
                    mma16816(accA[nt], Ahi, Bhi[nt][ks][0], Bhi[nt][ks][1]);
                    mma16816(accB[nt], Ahi, Blo[nt][ks][0], Blo[nt][ks][1]);
                    mma16816(accB[nt], Alo, Bhi[nt][ks][0], Bhi[nt][ks][1]);
                }
            }
            const int r0 = m0b + mrow + (lane >> 2);
            const int r1 = r0 + 8;
            #pragma unroll
            for (int nt = 0; nt < 2; nt++) {
                const int col = cg * 16 + nt * 8 + (lane & 3) * 2;
                float2 e0 = make_float2(accA[nt][0] + accB[nt][0], accA[nt][1] + accB[nt][1]);
                float2 e1 = make_float2(accA[nt][2] + accB[nt][2], accA[nt][3] + accB[nt][3]);
                if (MODE == 0) {
                    if (bias) {
                        float2 bv = *(const float2*)&bias[col];
                        e0.x += bv.x; e0.y += bv.y; e1.x += bv.x; e1.y += bv.y;
                    }
                } else {
                    if (r0 < M) {
                        float2 t1 = __ldg((const float2*)&tR[rr0 * 64 + col]);
                        float2 t2 = __ldg((const float2*)&tQ[q0 * 64 + col]);
                        e0.x += t1.x + t2.x; e0.y += t1.y + t2.y;
                    }
                    if (r1 < M) {
                        float2 t1 = __ldg((const float2*)&tR[rr1 * 64 + col]);
                        float2 t2 = __ldg((const float2*)&tQ[q1 * 64 + col]);
                        e1.x += t1.x + t2.x; e1.y += t1.y + t2.y;
                    }
                }
                if (r0 < M) *(float2*)&out[(size_t)r0 * 64 + col] = e0;
                if (r1 < M) *(float2*)&out[(size_t)r1 * 64 + col] = e1;
            }
            if (MODE == 1) {
                rr0 += 16; if (rr0 >= R) { rr0 -= R; q0++; }
                rr1 += 16; if (rr1 >= R) { rr1 -= R; q1++; }
            }
        }
    };

    // ---- persistent pipelined loop ----
    int tile = tile0;
    if (tile < tiles) {
        float4 v[8];
        stage_load(tile, v);
        stage_store(v, 0);
    }
    __syncthreads();
    int cur = 0;
    while (tile < tiles) {
        const int nxt = tile + stride;
        const bool have = (nxt < tiles);
        float4 v[8];
        if (have) stage_load(nxt, v);
        mma_epilogue(cur, tile * 128);
        if (have) stage_store(v, cur ^ 1);
        __syncthreads();
        cur ^= 1;
        tile = nxt;
    }
}

// ---- global wrappers ----
__global__ __launch_bounds__(256, 2)
void gemm_tc0(const float* __restrict__ X, const float* __restrict__ W,
              const float* __restrict__ bias, float* __restrict__ out,
              int M, float4* __restrict__ zbuf, int tiles)
{
    gemm_body<0>(X, nullptr, nullptr, W, bias, nullptr, nullptr,
                 out, M, 1, zbuf, tiles, blockIdx.x, gridDim.x);
}

__global__ __launch_bounds__(256, 2)
void gemm_tc1(const float* __restrict__ qe, const float* __restrict__ re,
              const float* __restrict__ W, const float* __restrict__ tR,
              const float* __restrict__ tQ, float* __restrict__ out,
              int M, int R, int tiles)
{
    gemm_body<1>(nullptr, qe, re, W, nullptr, tR, tQ,
                 out, M, R, nullptr, tiles, blockIdx.x, gridDim.x);
}

// Two independent small MODE-0 GEMMs in one launch (CTA-partitioned).
__global__ __launch_bounds__(256, 2)
void gemm_small_dual(const float* __restrict__ X1, const float* __restrict__ W1,
                     float* __restrict__ out1, int M1, int tiles1,
                     const float* __restrict__ X2, const float* __restrict__ W2,
                     float* __restrict__ out2, int M2, int tiles2)
{
    if ((int)blockIdx.x < tiles1)
        gemm_body<0>(X1, nullptr, nullptr, W1, nullptr, nullptr, nullptr,
                     out1, M1, 1, nullptr, tiles1, blockIdx.x, 1 << 20);
    else
        gemm_body<0>(X2, nullptr, nullptr, W2, nullptr, nullptr, nullptr,
                     out2, M2, 1, nullptr, tiles2, blockIdx.x - tiles1, 1 << 20);
}

// -----------------------------------------------------------------------------
// Edge kernel: half-warp (16 lanes) per edge, float4 per lane.
// -----------------------------------------------------------------------------
__global__ __launch_bounds__(256)
void edge_kernel(const int* __restrict__ edges,
                 const float* __restrict__ hidden,
                 const float* __restrict__ rela,
                 const float* __restrict__ wa_W,
                 const float* __restrict__ wa_b,
                 const float* __restrict__ tS,
                 const float* __restrict__ tQR,
                 float* __restrict__ agg,
                 float* __restrict__ alpha_out,
                 int E, int R)
{
    const int t = blockIdx.x * 256 + threadIdx.x;
    const int e = t >> 4;
    if (e >= E) return;
    const int sl = t & 15;

    const int* er = edges + (size_t)e * 6;
    const int q = __ldg(er + 0);
    const int r = __ldg(er + 2);
    const int s = __ldg(er + 4);
    const int o = __ldg(er + 5);

    float4 g   = __ldg(&((const float4*)tS)[(size_t)s * 16 + sl]);
    float4 p2  = __ldg(&((const float4*)tQR)[((size_t)q * R + r) * 16 + sl]);
    float4 hs  = __ldg(&((const float4*)hidden)[(size_t)s * 16 + sl]);
    float4 hr  = __ldg(&((const float4*)rela)[(size_t)r * 16 + sl]);
    float4 wa  = __ldg(&((const float4*)wa_W)[sl]);

    float px = fmaxf(g.x + p2.x, 0.f);
    float py = fmaxf(g.y + p2.y, 0.f);
    float pz = fmaxf(g.z + p2.z, 0.f);
    float pw = fmaxf(g.w + p2.w, 0.f);

    float part = fmaf(px, wa.x, fmaf(py, wa.y, fmaf(pz, wa.z, pw * wa.w)));
    #pragma unroll
    for (int off = 8; off; off >>= 1)
        part += __shfl_xor_sync(0xffffffffu, part, off);

    float alpha = 1.0f / (1.0f + __expf(-(part + __ldg(wa_b))));
    if (sl == 0) alpha_out[e] = alpha;

    float4 m;
    m.x = alpha * hs.x * hr.x;
    m.y = alpha * hs.y * hr.y;
    m.z = alpha * hs.z * hr.z;
    m.w = alpha * hs.w * hr.w;

    float* dst = &agg[(size_t)o * 64 + sl * 4];
    asm volatile("red.global.add.v4.f32 [%0], {%1, %2, %3, %4};"
                 :: "l"(dst), "f"(m.x), "f"(m.y), "f"(m.z), "f"(m.w) : "memory");
}

// -----------------------------------------------------------------------------
extern "C" void kernel_launch(void* const* d_in, const int* in_sizes, int n_in,
                              void* d_out, int out_size)
{
    const float* q_emb  = (const float*)d_in[1];
    const float* rela   = (const float*)d_in[2];
    const float* hidden = (const float*)d_in[3];
    const int*   edges  = (const int*)d_in[4];
    const float* Ws_W   = (const float*)d_in[6];
    const float* Ws_b   = (const float*)d_in[7];
    const float* Wr_W   = (const float*)d_in[8];
    const float* Wq_W   = (const float*)d_in[9];
    const float* Wqr_W  = (const float*)d_in[10];
    const float* wa_W   = (const float*)d_in[11];
    const float* wa_b   = (const float*)d_in[12];
    const float* Wh_W   = (const float*)d_in[13];

    const int Q = in_sizes[0];
    const int R = in_sizes[2] / 64;
    const int N = in_sizes[3] / 64;
    const int E = in_sizes[4] / 6;

    float* out = (float*)d_out;
    float* alpha_out = out + (size_t)N * 64;

    float *tS, *tR, *tQ, *tQR, *agg;
    cudaGetSymbolAddress((void**)&tS,  g_tableS);
    cudaGetSymbolAddress((void**)&tR,  g_tableR);
    cudaGetSymbolAddress((void**)&tQ,  g_tableQ);
    cudaGetSymbolAddress((void**)&tQR, g_tableQR);
    cudaGetSymbolAddress((void**)&agg, g_agg);

    const int SMEM = 65536;   // 2 x (hi 16KB + lo 16KB)
    cudaFuncSetAttribute(gemm_tc0, cudaFuncAttributeMaxDynamicSharedMemorySize, SMEM);
    cudaFuncSetAttribute(gemm_tc1, cudaFuncAttributeMaxDynamicSharedMemorySize, SMEM);
    cudaFuncSetAttribute(gemm_small_dual, cudaFuncAttributeMaxDynamicSharedMemorySize, SMEM);

    auto tiles_of = [](int M) { return (M + 127) / 128; };
    auto grid_of  = [&](int M) { int t = tiles_of(M); return t < 296 ? t : 296; };

    // Small tables (tR, tQ) in ONE launch — inputs to the QR fold
    const int tilesR = tiles_of(R), tilesQ = tiles_of(Q);
    gemm_small_dual<<<tilesR + tilesQ, 256, SMEM>>>(
        rela, Wr_W, tR, R, tilesR,
        q_emb, Wq_W, tQ, Q, tilesQ);

    // Big precomputes (tS pass also zeroes agg rows)
    gemm_tc0<<<grid_of(N), 256, SMEM>>>(hidden, Ws_W, Ws_b, tS, N,
                                        (float4*)agg, tiles_of(N));
    gemm_tc1<<<grid_of(Q * R), 256, SMEM>>>(q_emb, rela, Wqr_W, tR, tQ,
                                            tQR, Q * R, R, tiles_of(Q * R));

    // Per-edge gather/gate/scatter (half-warp per edge)
    edge_kernel<<<(E * 16 + 255) / 256, 256>>>(edges, hidden, rela, wa_W, wa_b,
                                               tS, tQR, agg, alpha_out, E, R);

    // Final projection: hidden_new = agg @ Wh^T
    gemm_tc0<<<grid_of(N), 256, SMEM>>>(agg, Wh_W, nullptr, out, N,
                                        nullptr, tiles_of(N));
}